// round 12
// baseline (speedup 1.0000x reference)
#include <cuda_runtime.h>
#include <cstdint>

// Problem constants (fixed: midis_out is (16, 11, 65536) fp32, LST=64)
#define NB      16
#define NI      11
#define NT      65536
#define LSTLEN  64
#define CHUNK   512
#define THREADS 256
#define NCHUNK  (NT / CHUNK)    // 128

__device__ __forceinline__ void ce(float& a, float& b) {
    const float lo = fminf(a, b), hi = fmaxf(a, b);
    a = lo; b = hi;
}

// Optimal 11-input sorting network (35 CE, depth 8), ascending.
__device__ __forceinline__ void sort11(float z[NI]) {
    ce(z[0],z[9]); ce(z[1],z[6]); ce(z[2],z[4]); ce(z[3],z[7]); ce(z[5],z[8]);
    ce(z[0],z[1]); ce(z[3],z[5]); ce(z[4],z[10]); ce(z[6],z[9]); ce(z[7],z[8]);
    ce(z[1],z[3]); ce(z[2],z[5]); ce(z[4],z[7]); ce(z[8],z[10]);
    ce(z[0],z[4]); ce(z[1],z[2]); ce(z[3],z[7]); ce(z[5],z[9]); ce(z[6],z[8]);
    ce(z[0],z[1]); ce(z[2],z[6]); ce(z[4],z[5]); ce(z[7],z[8]); ce(z[9],z[10]);
    ce(z[2],z[4]); ce(z[3],z[6]); ce(z[5],z[7]); ce(z[8],z[9]);
    ce(z[1],z[2]); ce(z[3],z[4]); ce(z[5],z[6]); ce(z[7],z[8]);
    ce(z[2],z[3]); ce(z[4],z[5]); ce(z[6],z[7]);
}

// Exact sparsemax tau over 11 values (destroys z).
// tau* = max_{k=1..d} (csum_k - 1)/k over the DESCENDING cumsum.
__device__ __forceinline__ float sparsemax11_tau(float z[NI]) {
    sort11(z);
    float cs  = z[NI - 1];
    float tau = cs - 1.0f;
    #pragma unroll
    for (int k = 2; k <= NI; ++k) {
        cs += z[NI - k];
        const float rk = 1.0f / (float)k;          // compile-time constant
        tau = fmaxf(tau, fmaf(cs, rk, -rk));       // (cs-1)/k
    }
    return tau;
}

// Warp-collective Michelot over the 64 values (x0, x1) held across 32 lanes.
// Safe warm start tau0 = max-1 (tau* >= max-1 since max output <= 1).
// 2 unconditional iterations, then a convergence-checked guard loop; every
// reduction result is warp-uniform (whole warp works one row), so the guard
// has zero divergence. Counts via ballot+popc (uniform by construction).
__device__ __forceinline__ float tau_time_warp(float x0, float x1) {
    float m = fmaxf(x0, x1);
    #pragma unroll
    for (int o = 16; o; o >>= 1)
        m = fmaxf(m, __shfl_xor_sync(0xFFFFFFFFu, m, o));

    float tau = m - 1.0f;
    int k = 65;                                  // sentinel > 64

    #pragma unroll
    for (int it = 0; it < 2; ++it) {
        const bool p0 = x0 > tau, p1 = x1 > tau;
        float ss = (p0 ? x0 : 0.0f) + (p1 ? x1 : 0.0f);
        #pragma unroll
        for (int o = 16; o; o >>= 1)
            ss += __shfl_xor_sync(0xFFFFFFFFu, ss, o);
        k = __popc(__ballot_sync(0xFFFFFFFFu, p0))
          + __popc(__ballot_sync(0xFFFFFFFFu, p1));
        tau = __fdividef(ss - 1.0f, (float)k);
    }

    #pragma unroll 1
    for (;;) {
        const bool p0 = x0 > tau, p1 = x1 > tau;
        const int kn = __popc(__ballot_sync(0xFFFFFFFFu, p0))
                     + __popc(__ballot_sync(0xFFFFFFFFu, p1));
        if (kn >= k) break;                      // support stable -> exact
        float ss = (p0 ? x0 : 0.0f) + (p1 ? x1 : 0.0f);
        #pragma unroll
        for (int o = 16; o; o >>= 1)
            ss += __shfl_xor_sync(0xFFFFFFFFu, ss, o);
        tau = __fdividef(ss - 1.0f, (float)kn);
        k = kn;
    }
    return tau;
}

// Single fused kernel: no SMEM, no __syncthreads, input read ONCE.
// Thread -> 2 adjacent columns; warp -> 64 contiguous columns = exactly one
// 64-length time block, for all 11 instruments, entirely in registers.
__global__ __launch_bounds__(THREADS)
void multiply_sparsemax_kernel(const float* __restrict__ in,
                               float* __restrict__ out)
{
    const int tid = threadIdx.x;
    const int b = blockIdx.x / NCHUNK;
    const int c = blockIdx.x % NCHUNK;
    const int t0 = tid * 2;
    const unsigned base = (unsigned)(b * NI) * NT + (unsigned)(c * CHUNK) + (unsigned)t0;

    // Load tile slice: 11 float2 per thread (coalesced per row)
    float2 v[NI];
    #pragma unroll
    for (int i = 0; i < NI; ++i)
        v[i] = *(const float2*)(in + base + (unsigned)(i * NT));

    // Instrument sparsemax for both columns (sort + max-formula, per-thread)
    float ta, tb;
    {
        float za[NI], zb[NI];
        #pragma unroll
        for (int i = 0; i < NI; ++i) { za[i] = v[i].x; zb[i] = v[i].y; }
        ta = sparsemax11_tau(za);
        tb = sparsemax11_tau(zb);
    }

    // Per instrument: warp-collective time-block tau, then write output row
    #pragma unroll
    for (int i = 0; i < NI; ++i) {
        const float tt = tau_time_warp(v[i].x, v[i].y);
        float2 r;
        r.x = fmaxf(v[i].x - ta, 0.0f) * fmaxf(v[i].x - tt, 0.0f);
        r.y = fmaxf(v[i].y - tb, 0.0f) * fmaxf(v[i].y - tt, 0.0f);
        *(float2*)(out + base + (unsigned)(i * NT)) = r;
    }
}

extern "C" void kernel_launch(void* const* d_in, const int* in_sizes, int n_in,
                              void* d_out, int out_size)
{
    const float* in = (const float*)d_in[0];
    float* out = (float*)d_out;
    multiply_sparsemax_kernel<<<NB * NCHUNK, THREADS>>>(in, out);
}

// round 13
// speedup vs baseline: 1.1253x; 1.1253x over previous
#include <cuda_runtime.h>
#include <cstdint>

// Problem constants (fixed: midis_out is (16, 11, 65536) fp32, LST=64)
#define NB      16
#define NI      11
#define NT      65536
#define LSTLEN  64
#define NBLK    (NB * NI * (NT / LSTLEN))   // 180224 time-blocks total
#define THREADS 256
#define K2THREADS 512
#define CHUNK   512                          // columns per CTA in kernel 2
#define NCHUNK  (NT / CHUNK)                 // 128

// Scratch for per-64-block taus (allocation-free: device global)
__device__ float g_tau_time[NBLK];

// ============================ Kernel 1 =====================================
// Exact sparsemax tau over one 64-block held as 8 elems/lane across an
// 8-lane segment. Michelot from safe warm start tau0 = max-1 (tau* >= max-1
// since max output <= 1): 2 unconditional iterations + convergence-checked
// guard loop (the check IS a full pass -> exact).
__device__ __forceinline__ float tau64_seg(const float z[8]) {
    float m = fmaxf(fmaxf(fmaxf(z[0], z[1]), fmaxf(z[2], z[3])),
                    fmaxf(fmaxf(z[4], z[5]), fmaxf(z[6], z[7])));
    #pragma unroll
    for (int o = 4; o; o >>= 1)
        m = fmaxf(m, __shfl_xor_sync(0xFFFFFFFFu, m, o));

    float tau = m - 1.0f;
    float cf  = 0.0f;

    #pragma unroll
    for (int it = 0; it < 2; ++it) {
        float ss = 0.0f; cf = 0.0f;
        #pragma unroll
        for (int j = 0; j < 8; ++j)
            if (z[j] > tau) { ss += z[j]; cf += 1.0f; }
        #pragma unroll
        for (int o = 4; o; o >>= 1) {
            ss += __shfl_xor_sync(0xFFFFFFFFu, ss, o);
            cf += __shfl_xor_sync(0xFFFFFFFFu, cf, o);
        }
        tau = __fdividef(ss - 1.0f, cf);
    }

    int k = (int)cf;
    #pragma unroll 1
    for (;;) {
        float ss = 0.0f, c2 = 0.0f;
        #pragma unroll
        for (int j = 0; j < 8; ++j)
            if (z[j] > tau) { ss += z[j]; c2 += 1.0f; }
        #pragma unroll
        for (int o = 4; o; o >>= 1) {
            ss += __shfl_xor_sync(0xFFFFFFFFu, ss, o);
            c2 += __shfl_xor_sync(0xFFFFFFFFu, c2, o);
        }
        const int kn = (int)c2;
        const bool conv = (kn >= k);
        if (__all_sync(0xFFFFFFFFu, conv)) break;
        if (!conv) { tau = __fdividef(ss - 1.0f, c2); k = kn; }
    }
    return tau;
}

// One warp = 8 blocks (two per 8-lane segment); ALL loads issued up front
// for MLP=4 per thread, then both reductions.
__global__ __launch_bounds__(THREADS)
void tau_time_kernel(const float* __restrict__ in)
{
    const int lane = threadIdx.x & 31;
    const int gwarp = (blockIdx.x * (THREADS / 32)) + (threadIdx.x >> 5);
    const int seg = lane >> 3;
    const int sl  = lane & 7;

    const int blkA = gwarp * 8 + seg;        // NBLK divisible by 8
    const int blkB = blkA + 4;

    const float* pA = in + (size_t)blkA * LSTLEN + sl * 8;
    const float* pB = in + (size_t)blkB * LSTLEN + sl * 8;
    const float4 a0 = *(const float4*)pA;
    const float4 a1 = *(const float4*)(pA + 4);
    const float4 b0 = *(const float4*)pB;
    const float4 b1 = *(const float4*)(pB + 4);

    const float zA[8] = {a0.x, a0.y, a0.z, a0.w, a1.x, a1.y, a1.z, a1.w};
    const float zB[8] = {b0.x, b0.y, b0.z, b0.w, b1.x, b1.y, b1.z, b1.w};

    const float tauA = tau64_seg(zA);
    const float tauB = tau64_seg(zB);
    if (sl == 0) {
        g_tau_time[blkA] = tauA;
        g_tau_time[blkB] = tauB;
    }
}

// ============================ Kernel 2 =====================================

__device__ __forceinline__ void ce(float& a, float& b) {
    const float lo = fminf(a, b), hi = fmaxf(a, b);
    a = lo; b = hi;
}

// Optimal 11-input sorting network (35 CE, depth 8), ascending.
__device__ __forceinline__ void sort11(float z[NI]) {
    ce(z[0],z[9]); ce(z[1],z[6]); ce(z[2],z[4]); ce(z[3],z[7]); ce(z[5],z[8]);
    ce(z[0],z[1]); ce(z[3],z[5]); ce(z[4],z[10]); ce(z[6],z[9]); ce(z[7],z[8]);
    ce(z[1],z[3]); ce(z[2],z[5]); ce(z[4],z[7]); ce(z[8],z[10]);
    ce(z[0],z[4]); ce(z[1],z[2]); ce(z[3],z[7]); ce(z[5],z[9]); ce(z[6],z[8]);
    ce(z[0],z[1]); ce(z[2],z[6]); ce(z[4],z[5]); ce(z[7],z[8]); ce(z[9],z[10]);
    ce(z[2],z[4]); ce(z[3],z[6]); ce(z[5],z[7]); ce(z[8],z[9]);
    ce(z[1],z[2]); ce(z[3],z[4]); ce(z[5],z[6]); ce(z[7],z[8]);
    ce(z[2],z[3]); ce(z[4],z[5]); ce(z[6],z[7]);
}

// Exact sparsemax tau over 11 values (destroys z).
// tau* = max_{k=1..d} (csum_k - 1)/k over the DESCENDING cumsum.
__device__ __forceinline__ float sparsemax11_tau(float z[NI]) {
    sort11(z);
    float cs  = z[NI - 1];
    float tau = cs - 1.0f;
    #pragma unroll
    for (int k = 2; k <= NI; ++k) {
        cs += z[NI - k];
        const float rk = 1.0f / (float)k;          // compile-time constant
        tau = fmaxf(tau, fmaf(cs, rk, -rk));       // (cs-1)/k
    }
    return tau;
}

// One column per thread, 512-thread CTAs: low register pressure -> high
// occupancy for latency hiding. No SMEM, no barriers. Warp covers 32
// adjacent columns (within one 64-block -> tau_time loads warp-uniform).
__global__ __launch_bounds__(K2THREADS)
void sparsemax_mul_kernel(const float* __restrict__ in,
                          float* __restrict__ out)
{
    const int tid = threadIdx.x;
    const int b = blockIdx.x / NCHUNK;
    const int c = blockIdx.x % NCHUNK;
    const unsigned base = (unsigned)(b * NI) * NT + (unsigned)(c * CHUNK) + (unsigned)tid;

    float v[NI], z[NI];
    #pragma unroll
    for (int i = 0; i < NI; ++i) {
        v[i] = in[base + (unsigned)(i * NT)];
        z[i] = v[i];
    }
    const float ta = sparsemax11_tau(z);     // destroys z

    // warp-uniform 64-block index within this (b, chunk)
    const int blkb = (b * NI) * (NT / LSTLEN) + c * (CHUNK / LSTLEN) + (tid >> 6);
    #pragma unroll
    for (int i = 0; i < NI; ++i) {
        const float tt = g_tau_time[blkb + i * (NT / LSTLEN)];
        out[base + (unsigned)(i * NT)] =
            fmaxf(v[i] - ta, 0.0f) * fmaxf(v[i] - tt, 0.0f);
    }
}

extern "C" void kernel_launch(void* const* d_in, const int* in_sizes, int n_in,
                              void* d_out, int out_size)
{
    const float* in = (const float*)d_in[0];
    float* out = (float*)d_out;
    // Kernel 1: 8 blocks per warp, 8 warps per CTA -> 64 blocks per CTA
    tau_time_kernel<<<NBLK / 64, THREADS>>>(in);
    // Kernel 2: 2048 CTAs x 512 threads, 1 column per thread
    sparsemax_mul_kernel<<<NB * NCHUNK, K2THREADS>>>(in, out);
}

// round 14
// speedup vs baseline: 1.1476x; 1.0198x over previous
#include <cuda_runtime.h>
#include <cstdint>

// Problem constants (fixed: midis_out is (16, 11, 65536) fp32, LST=64)
#define NB      16
#define NI      11
#define NT      65536
#define LSTLEN  64
#define NBLK    (NB * NI * (NT / LSTLEN))   // 180224 time-blocks total
#define THREADS 256
#define CHUNK   512                          // columns per CTA in kernel 2
#define NCHUNK  (NT / CHUNK)                 // 128
#define BPW     16                           // blocks per warp in kernel 1

// Scratch for per-64-block taus (allocation-free: device global)
__device__ float g_tau_time[NBLK];

// ============================ Kernel 1 =====================================
// tau for every 64-length time block (64 contiguous floats at in[blk*64]).
// One warp = 16 blocks: 4 per 8-lane segment, processed as 4 INDEPENDENT
// reduction chains interleaved at every step so the 3-shfl trees overlap.
// Michelot from safe warm start tau0 = max-1 (tau* >= max-1 since the max
// output <= 1): 2 warm iterations + convergence-checked guard (the check IS
// a full Michelot pass -> exact).
__global__ __launch_bounds__(THREADS)
void tau_time_kernel(const float* __restrict__ in)
{
    const int lane = threadIdx.x & 31;
    const int gwarp = (blockIdx.x * (THREADS / 32)) + (threadIdx.x >> 5);
    const int seg = lane >> 3;            // segment 0..3
    const int sl  = lane & 7;             // sub-lane 0..7

    const int blkBase = gwarp * BPW;      // NBLK divisible by 16

    // All loads up front: MLP = 8 independent LDG.128 per thread.
    float z[4][8];
    #pragma unroll
    for (int j = 0; j < 4; ++j) {
        const int blk = blkBase + j * 4 + seg;   // coalesced across the warp
        const float* p = in + (size_t)blk * LSTLEN + sl * 8;
        const float4 a = *(const float4*)p;
        const float4 b = *(const float4*)(p + 4);
        z[j][0]=a.x; z[j][1]=a.y; z[j][2]=a.z; z[j][3]=a.w;
        z[j][4]=b.x; z[j][5]=b.y; z[j][6]=b.z; z[j][7]=b.w;
    }

    // 4 independent max reductions, interleaved.
    float m[4];
    #pragma unroll
    for (int j = 0; j < 4; ++j)
        m[j] = fmaxf(fmaxf(fmaxf(z[j][0], z[j][1]), fmaxf(z[j][2], z[j][3])),
                     fmaxf(fmaxf(z[j][4], z[j][5]), fmaxf(z[j][6], z[j][7])));
    #pragma unroll
    for (int o = 4; o; o >>= 1) {
        #pragma unroll
        for (int j = 0; j < 4; ++j)
            m[j] = fmaxf(m[j], __shfl_xor_sync(0xFFFFFFFFu, m[j], o));
    }

    float tau[4], cf[4];
    #pragma unroll
    for (int j = 0; j < 4; ++j) tau[j] = m[j] - 1.0f;

    // 2 warm Michelot iterations, the 4 chains interleaved at every step.
    #pragma unroll
    for (int it = 0; it < 2; ++it) {
        float ss[4];
        #pragma unroll
        for (int j = 0; j < 4; ++j) {
            ss[j] = 0.0f; cf[j] = 0.0f;
            #pragma unroll
            for (int e = 0; e < 8; ++e)
                if (z[j][e] > tau[j]) { ss[j] += z[j][e]; cf[j] += 1.0f; }
        }
        #pragma unroll
        for (int o = 4; o; o >>= 1) {
            #pragma unroll
            for (int j = 0; j < 4; ++j) {
                ss[j] += __shfl_xor_sync(0xFFFFFFFFu, ss[j], o);
                cf[j] += __shfl_xor_sync(0xFFFFFFFFu, cf[j], o);
            }
        }
        #pragma unroll
        for (int j = 0; j < 4; ++j)
            tau[j] = __fdividef(ss[j] - 1.0f, cf[j]);
    }

    // Guard loops (rarely iterate; per-block, exactness guaranteed).
    #pragma unroll
    for (int j = 0; j < 4; ++j) {
        int k = (int)cf[j];
        #pragma unroll 1
        for (;;) {
            float ss = 0.0f, c2 = 0.0f;
            #pragma unroll
            for (int e = 0; e < 8; ++e)
                if (z[j][e] > tau[j]) { ss += z[j][e]; c2 += 1.0f; }
            #pragma unroll
            for (int o = 4; o; o >>= 1) {
                ss += __shfl_xor_sync(0xFFFFFFFFu, ss, o);
                c2 += __shfl_xor_sync(0xFFFFFFFFu, c2, o);
            }
            const int kn = (int)c2;
            const bool conv = (kn >= k);
            if (__all_sync(0xFFFFFFFFu, conv)) break;
            if (!conv) { tau[j] = __fdividef(ss - 1.0f, c2); k = kn; }
        }
    }

    if (sl == 0) {
        #pragma unroll
        for (int j = 0; j < 4; ++j)
            g_tau_time[blkBase + j * 4 + seg] = tau[j];
    }
}

// ============================ Kernel 2 (R11, measured 16.9us) ==============

__device__ __forceinline__ void ce(float& a, float& b) {
    const float lo = fminf(a, b), hi = fmaxf(a, b);
    a = lo; b = hi;
}

// Optimal 11-input sorting network (35 CE, depth 8), ascending.
__device__ __forceinline__ void sort11(float z[NI]) {
    ce(z[0],z[9]); ce(z[1],z[6]); ce(z[2],z[4]); ce(z[3],z[7]); ce(z[5],z[8]);
    ce(z[0],z[1]); ce(z[3],z[5]); ce(z[4],z[10]); ce(z[6],z[9]); ce(z[7],z[8]);
    ce(z[1],z[3]); ce(z[2],z[5]); ce(z[4],z[7]); ce(z[8],z[10]);
    ce(z[0],z[4]); ce(z[1],z[2]); ce(z[3],z[7]); ce(z[5],z[9]); ce(z[6],z[8]);
    ce(z[0],z[1]); ce(z[2],z[6]); ce(z[4],z[5]); ce(z[7],z[8]); ce(z[9],z[10]);
    ce(z[2],z[4]); ce(z[3],z[6]); ce(z[5],z[7]); ce(z[8],z[9]);
    ce(z[1],z[2]); ce(z[3],z[4]); ce(z[5],z[6]); ce(z[7],z[8]);
    ce(z[2],z[3]); ce(z[4],z[5]); ce(z[6],z[7]);
}

// Exact sparsemax tau over 11 values (destroys z).
// tau* = max_{k=1..d} (csum_k - 1)/k over the DESCENDING cumsum.
__device__ __forceinline__ float sparsemax11_tau(float z[NI]) {
    sort11(z);
    float cs  = z[NI - 1];
    float tau = cs - 1.0f;
    #pragma unroll
    for (int k = 2; k <= NI; ++k) {
        cs += z[NI - k];
        const float rk = 1.0f / (float)k;          // compile-time constant
        tau = fmaxf(tau, fmaf(cs, rk, -rk));       // (cs-1)/k
    }
    return tau;
}

// Per-column instrument sparsemax + multiply, no SMEM, no barriers.
// Thread -> 2 adjacent columns; warp -> 64 columns = exactly one 64-block,
// so the tau_time addresses are warp-uniform (broadcast loads, L1-hot).
__global__ __launch_bounds__(THREADS)
void sparsemax_mul_kernel(const float* __restrict__ in,
                          float* __restrict__ out)
{
    const int tid = threadIdx.x;
    const int b = blockIdx.x / NCHUNK;
    const int c = blockIdx.x % NCHUNK;
    const int t0 = tid * 2;
    const unsigned base = (unsigned)(b * NI) * NT + (unsigned)(c * CHUNK) + (unsigned)t0;

    float2 v[NI];
    float za[NI], zb[NI];
    #pragma unroll
    for (int i = 0; i < NI; ++i) {
        v[i] = *(const float2*)(in + base + (unsigned)(i * NT));
        za[i] = v[i].x; zb[i] = v[i].y;
    }
    const float ta = sparsemax11_tau(za);
    const float tb = sparsemax11_tau(zb);

    // warp-uniform 64-block index within this (b, chunk)
    const int blkb = (b * NI) * (NT / LSTLEN) + c * (CHUNK / LSTLEN) + (t0 >> 6);
    #pragma unroll
    for (int i = 0; i < NI; ++i) {
        const float tt = g_tau_time[blkb + i * (NT / LSTLEN)];
        float2 r;
        r.x = fmaxf(v[i].x - ta, 0.0f) * fmaxf(v[i].x - tt, 0.0f);
        r.y = fmaxf(v[i].y - tb, 0.0f) * fmaxf(v[i].y - tt, 0.0f);
        *(float2*)(out + base + (unsigned)(i * NT)) = r;
    }
}

extern "C" void kernel_launch(void* const* d_in, const int* in_sizes, int n_in,
                              void* d_out, int out_size)
{
    const float* in = (const float*)d_in[0];
    float* out = (float*)d_out;
    // Kernel 1: 16 blocks per warp, 8 warps per CTA -> 128 blocks per CTA
    tau_time_kernel<<<NBLK / (BPW * (THREADS / 32)), THREADS>>>(in);
    // Kernel 2: 2048 CTAs x 256 threads, 2 columns per thread
    sparsemax_mul_kernel<<<NB * NCHUNK, THREADS>>>(in, out);
}

// round 15
// speedup vs baseline: 1.2434x; 1.0835x over previous
#include <cuda_runtime.h>
#include <cstdint>

// Problem constants (fixed: midis_out is (16, 11, 65536) fp32, LST=64)
#define NB      16
#define NI      11
#define NT      65536
#define LSTLEN  64
#define NBLK    (NB * NI * (NT / LSTLEN))   // 180224 time-blocks total
#define THREADS 256
#define CHUNK   512                          // columns per CTA in kernel 2
#define NCHUNK  (NT / CHUNK)                 // 128

// Scratch for per-64-block taus (allocation-free: device global)
__device__ float g_tau_time[NBLK];

// ============================ Kernel 1 =====================================
// Exact sparsemax tau over one 64-block held as 8 elems/lane across an
// 8-lane segment. Michelot from safe warm start tau0 = max-1 (tau* >= max-1
// since max output <= 1): 2 unconditional iterations + convergence-checked
// guard loop (the check IS a full pass -> exact).
__device__ __forceinline__ float tau64_seg(const float z[8]) {
    float m = fmaxf(fmaxf(fmaxf(z[0], z[1]), fmaxf(z[2], z[3])),
                    fmaxf(fmaxf(z[4], z[5]), fmaxf(z[6], z[7])));
    #pragma unroll
    for (int o = 4; o; o >>= 1)
        m = fmaxf(m, __shfl_xor_sync(0xFFFFFFFFu, m, o));

    float tau = m - 1.0f;
    float cf  = 0.0f;

    #pragma unroll
    for (int it = 0; it < 2; ++it) {
        float ss = 0.0f; cf = 0.0f;
        #pragma unroll
        for (int j = 0; j < 8; ++j)
            if (z[j] > tau) { ss += z[j]; cf += 1.0f; }
        #pragma unroll
        for (int o = 4; o; o >>= 1) {
            ss += __shfl_xor_sync(0xFFFFFFFFu, ss, o);
            cf += __shfl_xor_sync(0xFFFFFFFFu, cf, o);
        }
        tau = __fdividef(ss - 1.0f, cf);
    }

    int k = (int)cf;
    #pragma unroll 1
    for (;;) {
        float ss = 0.0f, c2 = 0.0f;
        #pragma unroll
        for (int j = 0; j < 8; ++j)
            if (z[j] > tau) { ss += z[j]; c2 += 1.0f; }
        #pragma unroll
        for (int o = 4; o; o >>= 1) {
            ss += __shfl_xor_sync(0xFFFFFFFFu, ss, o);
            c2 += __shfl_xor_sync(0xFFFFFFFFu, c2, o);
        }
        const int kn = (int)c2;
        const bool conv = (kn >= k);
        if (__all_sync(0xFFFFFFFFu, conv)) break;
        if (!conv) { tau = __fdividef(ss - 1.0f, c2); k = kn; }
    }
    return tau;
}

// One warp = 8 blocks (two per 8-lane segment); ALL loads issued up front
// for MLP=4 per thread, then both reductions.
__global__ __launch_bounds__(THREADS)
void tau_time_kernel(const float* __restrict__ in)
{
    const int lane = threadIdx.x & 31;
    const int gwarp = (blockIdx.x * (THREADS / 32)) + (threadIdx.x >> 5);
    const int seg = lane >> 3;
    const int sl  = lane & 7;

    const int blkA = gwarp * 8 + seg;        // NBLK divisible by 8
    const int blkB = blkA + 4;

    const float* pA = in + (size_t)blkA * LSTLEN + sl * 8;
    const float* pB = in + (size_t)blkB * LSTLEN + sl * 8;
    const float4 a0 = *(const float4*)pA;
    const float4 a1 = *(const float4*)(pA + 4);
    const float4 b0 = *(const float4*)pB;
    const float4 b1 = *(const float4*)(pB + 4);

    const float zA[8] = {a0.x, a0.y, a0.z, a0.w, a1.x, a1.y, a1.z, a1.w};
    const float zB[8] = {b0.x, b0.y, b0.z, b0.w, b1.x, b1.y, b1.z, b1.w};

    const float tauA = tau64_seg(zA);
    const float tauB = tau64_seg(zB);
    if (sl == 0) {
        g_tau_time[blkA] = tauA;
        g_tau_time[blkB] = tauB;
    }
}

// ============================ Kernel 2 =====================================

__device__ __forceinline__ void ce(float& a, float& b) {
    const float lo = fminf(a, b), hi = fmaxf(a, b);
    a = lo; b = hi;
}

// Optimal 11-input sorting network (35 CE, depth 8), ascending.
__device__ __forceinline__ void sort11(float z[NI]) {
    ce(z[0],z[9]); ce(z[1],z[6]); ce(z[2],z[4]); ce(z[3],z[7]); ce(z[5],z[8]);
    ce(z[0],z[1]); ce(z[3],z[5]); ce(z[4],z[10]); ce(z[6],z[9]); ce(z[7],z[8]);
    ce(z[1],z[3]); ce(z[2],z[5]); ce(z[4],z[7]); ce(z[8],z[10]);
    ce(z[0],z[4]); ce(z[1],z[2]); ce(z[3],z[7]); ce(z[5],z[9]); ce(z[6],z[8]);
    ce(z[0],z[1]); ce(z[2],z[6]); ce(z[4],z[5]); ce(z[7],z[8]); ce(z[9],z[10]);
    ce(z[2],z[4]); ce(z[3],z[6]); ce(z[5],z[7]); ce(z[8],z[9]);
    ce(z[1],z[2]); ce(z[3],z[4]); ce(z[5],z[6]); ce(z[7],z[8]);
    ce(z[2],z[3]); ce(z[4],z[5]); ce(z[6],z[7]);
}

// Exact sparsemax tau over 11 values (destroys z).
// tau* = max_{k=1..d} (csum_k - 1)/k over the DESCENDING cumsum.
__device__ __forceinline__ float sparsemax11_tau(float z[NI]) {
    sort11(z);
    float cs  = z[NI - 1];
    float tau = cs - 1.0f;
    #pragma unroll
    for (int k = 2; k <= NI; ++k) {
        cs += z[NI - k];
        const float rk = 1.0f / (float)k;          // compile-time constant
        tau = fmaxf(tau, fmaf(cs, rk, -rk));       // (cs-1)/k
    }
    return tau;
}

// Per-column instrument sparsemax + multiply, no SMEM, no barriers.
// Thread -> 2 adjacent columns; warp -> 64 columns = exactly one 64-block,
// so the tau_time addresses are warp-uniform (broadcast loads, L1/L2-hot).
// Output stores use evict-first (__stcs): the output is never re-read, so
// keeping it OUT of L2 preserves the input's residency for the next
// replay's tau_time_kernel pass.
__global__ __launch_bounds__(THREADS)
void sparsemax_mul_kernel(const float* __restrict__ in,
                          float* __restrict__ out)
{
    const int tid = threadIdx.x;
    const int b = blockIdx.x / NCHUNK;
    const int c = blockIdx.x % NCHUNK;
    const int t0 = tid * 2;
    const unsigned base = (unsigned)(b * NI) * NT + (unsigned)(c * CHUNK) + (unsigned)t0;

    // Issue all data loads first (MLP=11)
    float2 v[NI];
    #pragma unroll
    for (int i = 0; i < NI; ++i)
        v[i] = *(const float2*)(in + base + (unsigned)(i * NT));

    // Issue tau_time loads early too (warp-uniform, L2-hot, consumed late)
    const int blkb = (b * NI) * (NT / LSTLEN) + c * (CHUNK / LSTLEN) + (t0 >> 6);
    float tt[NI];
    #pragma unroll
    for (int i = 0; i < NI; ++i)
        tt[i] = g_tau_time[blkb + i * (NT / LSTLEN)];

    // Instrument sparsemax for both columns (latency of tt loads hides here)
    float za[NI], zb[NI];
    #pragma unroll
    for (int i = 0; i < NI; ++i) { za[i] = v[i].x; zb[i] = v[i].y; }
    const float ta = sparsemax11_tau(za);
    const float tb = sparsemax11_tau(zb);

    #pragma unroll
    for (int i = 0; i < NI; ++i) {
        float2 r;
        r.x = fmaxf(v[i].x - ta, 0.0f) * fmaxf(v[i].x - tt[i], 0.0f);
        r.y = fmaxf(v[i].y - tb, 0.0f) * fmaxf(v[i].y - tt[i], 0.0f);
        __stcs((float2*)(out + base + (unsigned)(i * NT)), r);
    }
}

extern "C" void kernel_launch(void* const* d_in, const int* in_sizes, int n_in,
                              void* d_out, int out_size)
{
    const float* in = (const float*)d_in[0];
    float* out = (float*)d_out;
    // Kernel 1: 8 blocks per warp, 8 warps per CTA -> 64 blocks per CTA
    tau_time_kernel<<<NBLK / 64, THREADS>>>(in);
    // Kernel 2: 2048 CTAs x 256 threads, 2 columns per thread
    sparsemax_mul_kernel<<<NB * NCHUNK, THREADS>>>(in, out);
}